// round 6
// baseline (speedup 1.0000x reference)
#include <cuda_runtime.h>

// ---------------- problem constants ----------------
#define HW        512
#define PLANES    48          // 16 batch * 3 channels
#define NPIX      12582912.0  // 48*512*512
#define TW        64
#define TH        32
#define SW        74          // TW + 10
#define SH        42          // TH + 10
#define SSTR      76          // padded smem row stride (floats)
#define NTHREADS  320
#define NBLOCKS   6144        // 8*16*48

#define C1F 0.0001f
#define C2F 0.0009f

// Gaussian(sigma=1.5) centered at 5.5, normalized (sum = 0.99999982).
// Empirically validated (rel_err 7.9e-5). Tap precision is load-bearing:
// a -3.2e-4 tap-scale error amplifies ~500x through the C2=9e-4 term.
// __device__ constexpr + literal indices -> FFMA immediates (rt_SMSP=1).
__device__ constexpr float GW[11] = {
    0.00032030f, 0.00295566f, 0.01748770f, 0.06634250f, 0.16137290f,
    0.25168100f, 0.25168100f, 0.16137290f, 0.06634250f, 0.01748770f,
    0.00295566f
};

__device__ double g_part[NBLOCKS];
__device__ unsigned int g_count = 0;   // self-resetting ticket (atomicInc wraps)

// FMA-only reciprocal: magic seed + 3 Newton steps. Avoids MUFU.RCP
// (rt_SMSP=8 -> ~90us chip-wide floor at 12.6M divides).
__device__ __forceinline__ float fast_rcp(float d) {
    float r = __int_as_float(0x7EF311C3 - __float_as_int(d));
#pragma unroll
    for (int it = 0; it < 3; ++it) {
        float t = fmaf(-d, r, 1.0f);
        r = fmaf(r, t, r);
    }
    return r;
}

#define SIN1(r, c)    s_in1[(r) * SSTR + (c)]
#define SIN2(r, c)    s_in2[(r) * SSTR + (c)]
#define SMID(q, r, c) s_mid[((q) * TH + (r)) * SSTR + (c)]

__global__ void __launch_bounds__(NTHREADS, 2)
ssim_main_kernel(const float* __restrict__ img1, const float* __restrict__ img2,
                 float* __restrict__ out) {
    extern __shared__ float smem[];
    float* s_in1 = smem;                         // SH * SSTR
    float* s_in2 = smem + SH * SSTR;             // SH * SSTR
    float* s_mid = smem + 2 * SH * SSTR;         // 5 * TH * SSTR

    const int tid   = threadIdx.x;
    const int plane = blockIdx.z;
    const int x0    = blockIdx.x * TW;
    const int y0    = blockIdx.y * TH;

    const float* __restrict__ p1 = img1 + (size_t)plane * HW * HW;
    const float* __restrict__ p2 = img2 + (size_t)plane * HW * HW;

    // ---------- Phase 1: load halo tiles (zero-padded borders) ----------
    // Thread owns one column (x = tid%74), strides rows by 4: one div/mod
    // total instead of one per element; loads stay coalesced across x.
    if (tid < 296) {
        const int x  = tid % 74;
        const int r0 = tid / 74;
        const int gx = x0 - 5 + x;
        const bool xin = (unsigned)gx < (unsigned)HW;
#pragma unroll
        for (int rr = 0; rr < 11; ++rr) {
            const int r = r0 + rr * 4;
            if (r < SH) {
                const int gy = y0 - 5 + r;
                float a = 0.f, b = 0.f;
                if (xin && (unsigned)gy < (unsigned)HW) {
                    const int gi = gy * HW + gx;
                    a = p1[gi];
                    b = p2[gi];
                }
                SIN1(r, x) = a;
                SIN2(r, x) = b;
            }
        }
    }
    __syncthreads();

    // ---------- Phase 2: vertical 11-tap conv, single sweep, 5 quantities ----
    // Merged (R3-style): one LDS pass over s_in, 40 live accumulators.
    // launch_bounds(320,2) allows up to 102 regs -> no spill.
    if (tid < 296) {                 // 74 columns * 4 row-groups of 8
        const int x  = tid % 74;
        const int yb = (tid / 74) * 8;

        float a0[8], a1[8], a2[8], a3[8], a4[8];
#pragma unroll
        for (int r = 0; r < 8; ++r) {
            a0[r] = 0.f; a1[r] = 0.f; a2[r] = 0.f; a3[r] = 0.f; a4[r] = 0.f;
        }
#pragma unroll
        for (int jj = 0; jj < 18; ++jj) {
            const float va  = SIN1(yb + jj, x);
            const float vb  = SIN2(yb + jj, x);
            const float vaa = va * va;
            const float vbb = vb * vb;
            const float vab = va * vb;
#pragma unroll
            for (int r = 0; r < 8; ++r) {
                const int j = jj - r;
                if (0 <= j && j < 11) {
                    a0[r] = fmaf(GW[j], va,  a0[r]);
                    a1[r] = fmaf(GW[j], vb,  a1[r]);
                    a2[r] = fmaf(GW[j], vaa, a2[r]);
                    a3[r] = fmaf(GW[j], vbb, a3[r]);
                    a4[r] = fmaf(GW[j], vab, a4[r]);
                }
            }
        }
#pragma unroll
        for (int r = 0; r < 8; ++r) {
            SMID(0, yb + r, x) = a0[r];
            SMID(1, yb + r, x) = a1[r];
            SMID(2, yb + r, x) = a2[r];
            SMID(3, yb + r, x) = a3[r];
            SMID(4, yb + r, x) = a4[r];
        }
    }
    __syncthreads();

    // ---------- Phase 3: horizontal 11-tap conv + SSIM ----------
    float lsum = 0.f;
    if (tid < 256) {                  // 32 rows * 8 column-groups of 8
        const int y  = tid >> 3;
        const int xb = (tid & 7) * 8;

        float o[5][8];
#pragma unroll
        for (int q = 0; q < 5; ++q) {
            const float4* vp = reinterpret_cast<const float4*>(&SMID(q, y, xb));
            float m[20];
#pragma unroll
            for (int k = 0; k < 5; ++k) {
                const float4 v = vp[k];
                m[4 * k + 0] = v.x;
                m[4 * k + 1] = v.y;
                m[4 * k + 2] = v.z;
                m[4 * k + 3] = v.w;
            }
#pragma unroll
            for (int r = 0; r < 8; ++r) {
                float s = GW[0] * m[r];
#pragma unroll
                for (int i = 1; i < 11; ++i) s = fmaf(GW[i], m[r + i], s);
                o[q][r] = s;
            }
        }
#pragma unroll
        for (int r = 0; r < 8; ++r) {
            const float mu1 = o[0][r], mu2 = o[1][r];
            const float e11 = o[2][r], e22 = o[3][r], e12 = o[4][r];
            const float m11 = mu1 * mu1;
            const float m22 = mu2 * mu2;
            const float m12 = mu1 * mu2;
            const float s1  = e11 - m11;
            const float s2  = e22 - m22;
            const float s12 = e12 - m12;
            const float num = fmaf(2.f, m12, C1F) * fmaf(2.f, s12, C2F);
            const float den = (m11 + m22 + C1F) * (s1 + s2 + C2F);
            lsum = fmaf(num, fast_rcp(den), lsum);
        }
    }

    // ---------- In-block reduction ----------
#pragma unroll
    for (int off = 16; off > 0; off >>= 1)
        lsum += __shfl_down_sync(0xffffffffu, lsum, off);

    __shared__ float  warp_sums[NTHREADS / 32];
    __shared__ unsigned s_last;
    const int wid  = tid >> 5;
    const int lane = tid & 31;
    if (lane == 0) warp_sums[wid] = lsum;
    __syncthreads();

    // ---------- Last-block-done global reduction (no 2nd kernel) ----------
    if (tid == 0) {
        float s = 0.f;
#pragma unroll
        for (int w = 0; w < NTHREADS / 32; ++w) s += warp_sums[w];
        const int bid = (blockIdx.z * gridDim.y + blockIdx.y) * gridDim.x + blockIdx.x;
        g_part[bid] = (double)s;
        __threadfence();
        // wraps to 0 when old == NBLOCKS-1 -> counter reset for next graph replay
        const unsigned ticket = atomicInc(&g_count, NBLOCKS - 1);
        s_last = (ticket == NBLOCKS - 1) ? 1u : 0u;
    }
    __syncthreads();

    if (s_last) {
        __threadfence();
        double d = 0.0;
        for (int i = tid; i < NBLOCKS; i += NTHREADS) d += g_part[i];
#pragma unroll
        for (int off = 16; off > 0; off >>= 1)
            d += __shfl_down_sync(0xffffffffu, d, off);
        __shared__ double wsum[NTHREADS / 32];
        if (lane == 0) wsum[wid] = d;
        __syncthreads();
        if (tid == 0) {
            double t = 0.0;
#pragma unroll
            for (int w = 0; w < NTHREADS / 32; ++w) t += wsum[w];
            out[0] = (float)(t * (1.0 / NPIX));
        }
    }
}

extern "C" void kernel_launch(void* const* d_in, const int* in_sizes, int n_in,
                              void* d_out, int out_size) {
    const float* img1 = (const float*)d_in[0];
    const float* img2 = (const float*)d_in[1];
    float* out = (float*)d_out;

    const int smem_bytes = (2 * SH * SSTR + 5 * TH * SSTR) * (int)sizeof(float); // 74176
    cudaFuncSetAttribute(ssim_main_kernel,
                         cudaFuncAttributeMaxDynamicSharedMemorySize, smem_bytes);

    dim3 grid(HW / TW, HW / TH, PLANES);   // 8 x 16 x 48
    ssim_main_kernel<<<grid, NTHREADS, smem_bytes>>>(img1, img2, out);
}

// round 7
// speedup vs baseline: 1.0251x; 1.0251x over previous
#include <cuda_runtime.h>

// ---------------- problem constants ----------------
#define HW        512
#define PLANES    48          // 16 batch * 3 channels
#define NPIX      12582912.0  // 48*512*512
#define TW        64
#define TH        32
#define HH        16          // half-tile height (s_mid halved -> 4 blocks/SM)
#define SW        74          // TW + 10
#define SH        42          // TH + 10
#define SSTR      76          // padded smem row stride (floats)
#define NTHREADS  320
#define NBLOCKS   6144        // 8*16*48

#define C1F 0.0001f
#define C2F 0.0009f

// Gaussian(sigma=1.5) centered at 5.5, normalized (sum = 0.99999982).
// Empirically validated (rel_err 7.9e-5). Tap precision is load-bearing:
// a -3.2e-4 tap-scale error amplifies ~500x through the C2=9e-4 term.
// __device__ constexpr + literal indices -> FFMA immediates (rt_SMSP=1).
__device__ constexpr float GW[11] = {
    0.00032030f, 0.00295566f, 0.01748770f, 0.06634250f, 0.16137290f,
    0.25168100f, 0.25168100f, 0.16137290f, 0.06634250f, 0.01748770f,
    0.00295566f
};

__device__ double g_part[NBLOCKS];
__device__ unsigned int g_count = 0;   // self-resetting ticket (atomicInc wraps)

// FMA-only reciprocal: magic seed + 2 Newton steps (e0~0.034 -> e0^4 ~ 1.4e-6,
// negligible vs fp32 conv error). Avoids MUFU.RCP (rt_SMSP=8 floor).
__device__ __forceinline__ float fast_rcp(float d) {
    float r = __int_as_float(0x7EF311C3 - __float_as_int(d));
#pragma unroll
    for (int it = 0; it < 2; ++it) {
        float t = fmaf(-d, r, 1.0f);
        r = fmaf(r, t, r);
    }
    return r;
}

#define SIN1(r, c)    s_in1[(r) * SSTR + (c)]
#define SIN2(r, c)    s_in2[(r) * SSTR + (c)]
#define SMID(q, r, c) s_mid[((q) * HH + (r)) * SSTR + (c)]  // r is half-local row

__global__ void __launch_bounds__(NTHREADS, 4)
ssim_main_kernel(const float* __restrict__ img1, const float* __restrict__ img2,
                 float* __restrict__ out) {
    extern __shared__ float smem[];
    float* s_in1 = smem;                         // SH * SSTR   (25,536 B total in)
    float* s_in2 = smem + SH * SSTR;
    float* s_mid = smem + 2 * SH * SSTR;         // 5 * HH * SSTR (24,320 B)

    const int tid   = threadIdx.x;
    const int plane = blockIdx.z;
    const int x0    = blockIdx.x * TW;
    const int y0    = blockIdx.y * TH;

    const float* __restrict__ p1 = img1 + (size_t)plane * HW * HW;
    const float* __restrict__ p2 = img2 + (size_t)plane * HW * HW;

    // ---------- Phase 1: load halo tiles (zero-padded borders) ----------
    if (tid < 296) {
        const int x  = tid % 74;
        const int r0 = tid / 74;
        const int gx = x0 - 5 + x;
        const bool xin = (unsigned)gx < (unsigned)HW;
#pragma unroll
        for (int rr = 0; rr < 11; ++rr) {
            const int r = r0 + rr * 4;
            if (r < SH) {
                const int gy = y0 - 5 + r;
                float a = 0.f, b = 0.f;
                if (xin && (unsigned)gy < (unsigned)HW) {
                    const int gi = gy * HW + gx;
                    a = p1[gi];
                    b = p2[gi];
                }
                SIN1(r, x) = a;
                SIN2(r, x) = b;
            }
        }
    }
    __syncthreads();

    float lsum = 0.f;

    // ---------- Two 16-row halves: s_mid is half-size -> 4 blocks/SM ----------
#pragma unroll
    for (int h = 0; h < 2; ++h) {
        const int yb0 = h * HH;

        // ---- Phase 2 (half): vertical 11-tap conv, 148 active threads ----
        // q-split {2,3}: peak 24 accumulators, fits the ~48-reg cap of
        // launch_bounds(320,4) without spills.
        if (tid < 148) {
            const int x  = tid % 74;
            const int g  = tid / 74;          // 0/1 -> rows g*8..g*8+7 of half
            const int yb = yb0 + g * 8;       // s_in row base
            const int lb = g * 8;             // s_mid local row base

            { // group A: q0 = conv(a), q1 = conv(b)
                float a0[8], a1[8];
#pragma unroll
                for (int r = 0; r < 8; ++r) { a0[r] = 0.f; a1[r] = 0.f; }
#pragma unroll
                for (int jj = 0; jj < 18; ++jj) {
                    const float va = SIN1(yb + jj, x);
                    const float vb = SIN2(yb + jj, x);
#pragma unroll
                    for (int r = 0; r < 8; ++r) {
                        const int j = jj - r;
                        if (0 <= j && j < 11) {
                            a0[r] = fmaf(GW[j], va, a0[r]);
                            a1[r] = fmaf(GW[j], vb, a1[r]);
                        }
                    }
                }
#pragma unroll
                for (int r = 0; r < 8; ++r) {
                    SMID(0, lb + r, x) = a0[r];
                    SMID(1, lb + r, x) = a1[r];
                }
            }
            { // group B: q2 = conv(a*a), q3 = conv(b*b), q4 = conv(a*b)
                float a2[8], a3[8], a4[8];
#pragma unroll
                for (int r = 0; r < 8; ++r) { a2[r] = 0.f; a3[r] = 0.f; a4[r] = 0.f; }
#pragma unroll
                for (int jj = 0; jj < 18; ++jj) {
                    const float va  = SIN1(yb + jj, x);
                    const float vb  = SIN2(yb + jj, x);
                    const float vaa = va * va;
                    const float vbb = vb * vb;
                    const float vab = va * vb;
#pragma unroll
                    for (int r = 0; r < 8; ++r) {
                        const int j = jj - r;
                        if (0 <= j && j < 11) {
                            a2[r] = fmaf(GW[j], vaa, a2[r]);
                            a3[r] = fmaf(GW[j], vbb, a3[r]);
                            a4[r] = fmaf(GW[j], vab, a4[r]);
                        }
                    }
                }
#pragma unroll
                for (int r = 0; r < 8; ++r) {
                    SMID(2, lb + r, x) = a2[r];
                    SMID(3, lb + r, x) = a3[r];
                    SMID(4, lb + r, x) = a4[r];
                }
            }
        }
        __syncthreads();

        // ---- Phase 3 (half): horizontal conv + SSIM, 128 active threads ----
        // Two 4-column passes keep peak regs ~36 (o[5][4] + m[16]).
        if (tid < 128) {
            const int y = tid >> 3;           // 0..15 (half-local row)
#pragma unroll
            for (int p = 0; p < 2; ++p) {
                const int xc = (tid & 7) * 8 + p * 4;

                float o[5][4];
#pragma unroll
                for (int q = 0; q < 5; ++q) {
                    const float4* vp = reinterpret_cast<const float4*>(&SMID(q, y, xc));
                    float m[16];
#pragma unroll
                    for (int k = 0; k < 4; ++k) {
                        const float4 v = vp[k];
                        m[4 * k + 0] = v.x;
                        m[4 * k + 1] = v.y;
                        m[4 * k + 2] = v.z;
                        m[4 * k + 3] = v.w;
                    }
#pragma unroll
                    for (int r = 0; r < 4; ++r) {
                        float s = GW[0] * m[r];
#pragma unroll
                        for (int i = 1; i < 11; ++i) s = fmaf(GW[i], m[r + i], s);
                        o[q][r] = s;
                    }
                }
#pragma unroll
                for (int r = 0; r < 4; ++r) {
                    const float mu1 = o[0][r], mu2 = o[1][r];
                    const float e11 = o[2][r], e22 = o[3][r], e12 = o[4][r];
                    const float m11 = mu1 * mu1;
                    const float m22 = mu2 * mu2;
                    const float m12 = mu1 * mu2;
                    const float s1  = e11 - m11;
                    const float s2  = e22 - m22;
                    const float s12 = e12 - m12;
                    const float num = fmaf(2.f, m12, C1F) * fmaf(2.f, s12, C2F);
                    const float den = (m11 + m22 + C1F) * (s1 + s2 + C2F);
                    lsum = fmaf(num, fast_rcp(den), lsum);
                }
            }
        }
        __syncthreads();   // protect s_mid before next half overwrites
    }

    // ---------- In-block reduction ----------
#pragma unroll
    for (int off = 16; off > 0; off >>= 1)
        lsum += __shfl_down_sync(0xffffffffu, lsum, off);

    __shared__ float  warp_sums[NTHREADS / 32];
    __shared__ unsigned s_last;
    const int wid  = tid >> 5;
    const int lane = tid & 31;
    if (lane == 0) warp_sums[wid] = lsum;
    __syncthreads();

    // ---------- Last-block-done global reduction (no 2nd kernel) ----------
    if (tid == 0) {
        float s = 0.f;
#pragma unroll
        for (int w = 0; w < NTHREADS / 32; ++w) s += warp_sums[w];
        const int bid = (blockIdx.z * gridDim.y + blockIdx.y) * gridDim.x + blockIdx.x;
        g_part[bid] = (double)s;
        __threadfence();
        const unsigned ticket = atomicInc(&g_count, NBLOCKS - 1);
        s_last = (ticket == NBLOCKS - 1) ? 1u : 0u;
    }
    __syncthreads();

    if (s_last) {
        __threadfence();
        double d = 0.0;
        for (int i = tid; i < NBLOCKS; i += NTHREADS) d += g_part[i];
#pragma unroll
        for (int off = 16; off > 0; off >>= 1)
            d += __shfl_down_sync(0xffffffffu, d, off);
        __shared__ double wsum[NTHREADS / 32];
        if (lane == 0) wsum[wid] = d;
        __syncthreads();
        if (tid == 0) {
            double t = 0.0;
#pragma unroll
            for (int w = 0; w < NTHREADS / 32; ++w) t += wsum[w];
            out[0] = (float)(t * (1.0 / NPIX));
        }
    }
}

extern "C" void kernel_launch(void* const* d_in, const int* in_sizes, int n_in,
                              void* d_out, int out_size) {
    const float* img1 = (const float*)d_in[0];
    const float* img2 = (const float*)d_in[1];
    float* out = (float*)d_out;

    const int smem_bytes = (2 * SH * SSTR + 5 * HH * SSTR) * (int)sizeof(float); // 49,856
    cudaFuncSetAttribute(ssim_main_kernel,
                         cudaFuncAttributeMaxDynamicSharedMemorySize, smem_bytes);

    dim3 grid(HW / TW, HW / TH, PLANES);   // 8 x 16 x 48
    ssim_main_kernel<<<grid, NTHREADS, smem_bytes>>>(img1, img2, out);
}